// round 14
// baseline (speedup 1.0000x reference)
#include <cuda_runtime.h>
#include <cuda_fp16.h>
#include <math.h>
#include <stdint.h>

#define N_TOT 8192
#define F_DIM 128
#define TBLK  64                 // 8192 / 128
#define NTILES (TBLK*(TBLK+1)/2) // 2080 upper-triangle tiles
#define TILEB 32768              // 128 rows x 256B (fp16), XOR-swizzled
#define SM_TOTAL (2 * TILEB)     // A + B = 64KB

// Device scratch (allocation-free rules)
__device__ __half g_xh[N_TOT * F_DIM];   // scaled normalized feats [N][F] fp16
__device__ float g_part[NTILES];

__device__ __forceinline__ uint32_t smem_u32(const void* p) {
    uint32_t a;
    asm("{ .reg .u64 t; cvta.to.shared.u64 t, %1; cvt.u32.u64 %0, t; }" : "=r"(a) : "l"(p));
    return a;
}
__device__ __forceinline__ float ex2a(float x) {
    float y; asm("ex2.approx.f32 %0, %1;" : "=f"(y) : "f"(x)); return y;
}
#define CPA16(dst, src) \
    asm volatile("cp.async.cg.shared.global [%0], [%1], 16;" :: "r"(dst), "l"(src))
#define LDS128(r0, r1, r2, r3, addr) \
    asm volatile("ld.shared.v4.u32 {%0,%1,%2,%3}, [%4];" \
                 : "=r"(r0), "=r"(r1), "=r"(r2), "=r"(r3) : "r"(addr))

// ---------------------------------------------------------------------------
// Kernel 1: normalize + fold sqrt(10/ln2) + fp16 convert (R13 version).
// ---------------------------------------------------------------------------
__global__ void __launch_bounds__(256) normalize_kernel(const float* __restrict__ x) {
    __shared__ float sm[8 * 130];

    const int tid = threadIdx.x;
    const int n0  = blockIdx.x * 8;
    const int b   = n0 >> 10;
    const int thw0 = n0 & 1023;
    const float* base = x + (size_t)b * 131072 + thw0;

    {
        int q = tid & 1;
        int f = tid >> 1;
        float4 v = *(const float4*)&base[(size_t)f * 1024 + q * 4];
        sm[(q * 4 + 0) * 130 + f] = v.x;
        sm[(q * 4 + 1) * 130 + f] = v.y;
        sm[(q * 4 + 2) * 130 + f] = v.z;
        sm[(q * 4 + 3) * 130 + f] = v.w;
    }
    __syncthreads();

    const int w    = tid >> 5;
    const int lane = tid & 31;
    const float* row = &sm[w * 130];

    float a0 = row[2 * lane];
    float a1 = row[2 * lane + 1];
    float b0 = row[64 + 2 * lane];
    float b1 = row[64 + 2 * lane + 1];

    float ss = a0 * a0 + a1 * a1 + b0 * b0 + b1 * b1;
#pragma unroll
    for (int off = 16; off > 0; off >>= 1)
        ss += __shfl_xor_sync(0xFFFFFFFFu, ss, off);

    float rn = (1.0f / fmaxf(sqrtf(ss), 1e-12f)) * 3.7982825f;  // sqrt(10/ln2)

    __half2 h0 = __floats2half2_rn(a0 * rn, a1 * rn);
    __half2 h1 = __floats2half2_rn(b0 * rn, b1 * rn);
    uint32_t* out = (uint32_t*)(g_xh + (size_t)(n0 + w) * F_DIM);
    out[lane]      = *(uint32_t*)&h0;
    out[32 + lane] = *(uint32_t*)&h1;
}

// ---------------------------------------------------------------------------
// Kernel 2: hybrid GEMM + fused exp2-sum.
// Tiles with (t & 7) == 7 run an HFMA2 (fma-pipe) SYRK; the rest run the
// proven mma.sync fp16 path. Both share smem loads + reduction.
// ---------------------------------------------------------------------------
__global__ void __launch_bounds__(512, 2) simexp_kernel() {
    extern __shared__ char smem[];
    const uint32_t sbase = smem_u32(smem);
    const int tid  = threadIdx.x;
    const int wid  = tid >> 5;
    const int lane = tid & 31;

    // linear tile id -> (bi, bj), bj >= bi
    int t = blockIdx.x;
    int bi = (int)((129.0f - sqrtf(16641.0f - 8.0f * (float)t)) * 0.5f);
    while ((bi + 1) * (129 - (bi + 1)) / 2 <= t) ++bi;
    while (bi * (129 - bi) / 2 > t) --bi;
    const int bj = bi + (t - bi * (129 - bi) / 2);
    const bool diag = (bi == bj);

    // cooperative tile loads (2048 x 16B chunks over 512 threads)
    {
        const char* gA = (const char*)(g_xh + (size_t)bi * 128 * F_DIM);
#pragma unroll
        for (int it = 0; it < 4; ++it) {
            int idx = it * 512 + tid;
            int r = idx >> 4, q = idx & 15;
            CPA16(sbase + r * 256 + ((q ^ (r & 7)) << 4), gA + (size_t)idx * 16);
        }
        if (!diag) {
            const char* gB = (const char*)(g_xh + (size_t)bj * 128 * F_DIM);
#pragma unroll
            for (int it = 0; it < 4; ++it) {
                int idx = it * 512 + tid;
                int r = idx >> 4, q = idx & 15;
                CPA16(sbase + TILEB + r * 256 + ((q ^ (r & 7)) << 4), gB + (size_t)idx * 16);
            }
        }
        asm volatile("cp.async.commit_group;");
        asm volatile("cp.async.wait_group 0;" ::: "memory");
    }
    __syncthreads();

    const uint32_t aBase = sbase;
    const uint32_t bBase = diag ? sbase : (sbase + TILEB);

    float s = 0.f;

    if ((t & 7) == 7) {
        // ---------------- FMA-pipe path (HFMA2 SYRK) ----------------
        // thread: rows r0..r0+3, cols c0..c0+3, two column passes.
        const int tr = tid >> 4;          // 0..31 -> rows 4*tr
        const int tc = tid & 15;          // 0..15 -> cols within pass
        const int r0 = tr * 4;
#pragma unroll
        for (int pass = 0; pass < 2; ++pass) {
            const int c0 = pass * 64 + tc * 4;
            __half2 acc[4][4];
#pragma unroll
            for (int i = 0; i < 4; ++i)
#pragma unroll
                for (int j = 0; j < 4; ++j) acc[i][j] = __half2half2(__ushort_as_half(0));

#pragma unroll
            for (int q = 0; q < 16; ++q) {           // 16B k-chunks
                uint32_t av[4][4];
#pragma unroll
                for (int i = 0; i < 4; ++i) {
                    int r = r0 + i;
                    uint32_t addr = aBase + r * 256 + ((q ^ (r & 7)) << 4);
                    LDS128(av[i][0], av[i][1], av[i][2], av[i][3], addr);
                }
#pragma unroll
                for (int j = 0; j < 4; ++j) {
                    int c = c0 + j;
                    uint32_t bv0, bv1, bv2, bv3;
                    uint32_t addr = bBase + c * 256 + ((q ^ (c & 7)) << 4);
                    LDS128(bv0, bv1, bv2, bv3, addr);
                    __half2 b0 = *(__half2*)&bv0, b1 = *(__half2*)&bv1;
                    __half2 b2 = *(__half2*)&bv2, b3 = *(__half2*)&bv3;
#pragma unroll
                    for (int i = 0; i < 4; ++i) {
                        acc[i][j] = __hfma2(*(__half2*)&av[i][0], b0, acc[i][j]);
                        acc[i][j] = __hfma2(*(__half2*)&av[i][1], b1, acc[i][j]);
                        acc[i][j] = __hfma2(*(__half2*)&av[i][2], b2, acc[i][j]);
                        acc[i][j] = __hfma2(*(__half2*)&av[i][3], b3, acc[i][j]);
                    }
                }
            }
            // epilogue for this pass
#pragma unroll
            for (int i = 0; i < 4; ++i)
#pragma unroll
                for (int j = 0; j < 4; ++j) {
                    int r_ = r0 + i, c_ = c0 + j;
                    if (diag && r_ == c_) continue;
                    float2 f = __half22float2(acc[i][j]);
                    s += ex2a(f.x + f.y);
                }
        }
    } else {
        // ---------------- tensor path (verbatim R12/R13) ----------------
        const int wm = (wid >> 2) * 32;
        const int wn = (wid & 3) * 32;
        const int g  = lane >> 3;
        const int lr = lane & 7;
        const int lrow = lane >> 2;
        const int lcol = (lane & 3) * 2;

        uint32_t acc[2][4][2];
#pragma unroll
        for (int mt = 0; mt < 2; ++mt)
#pragma unroll
            for (int nt = 0; nt < 4; ++nt) {
                acc[mt][nt][0] = 0u;
                acc[mt][nt][1] = 0u;
            }

#pragma unroll
        for (int kc = 0; kc < 8; ++kc) {
            const int qa = kc * 2 + (g >> 1);
            const int qb = kc * 2 + (g & 1);
            uint32_t a[2][4];
#pragma unroll
            for (int mt = 0; mt < 2; ++mt) {
                int row = wm + mt * 16 + (g & 1) * 8 + lr;
                uint32_t addr = aBase + row * 256 + ((qa ^ lr) << 4);
                asm volatile("ldmatrix.sync.aligned.m8n8.x4.shared.b16 {%0,%1,%2,%3}, [%4];"
                             : "=r"(a[mt][0]), "=r"(a[mt][1]), "=r"(a[mt][2]), "=r"(a[mt][3])
                             : "r"(addr));
            }
            uint32_t bf[2][4];
#pragma unroll
            for (int np = 0; np < 2; ++np) {
                int row = wn + np * 16 + (g >> 1) * 8 + lr;
                uint32_t addr = bBase + row * 256 + ((qb ^ lr) << 4);
                asm volatile("ldmatrix.sync.aligned.m8n8.x4.shared.b16 {%0,%1,%2,%3}, [%4];"
                             : "=r"(bf[np][0]), "=r"(bf[np][1]), "=r"(bf[np][2]), "=r"(bf[np][3])
                             : "r"(addr));
            }
#pragma unroll
            for (int mt = 0; mt < 2; ++mt)
#pragma unroll
                for (int nt = 0; nt < 4; ++nt) {
                    uint32_t b0 = bf[nt >> 1][(nt & 1) * 2];
                    uint32_t b1 = bf[nt >> 1][(nt & 1) * 2 + 1];
                    asm volatile(
                        "mma.sync.aligned.m16n8k16.row.col.f16.f16.f16.f16 "
                        "{%0,%1}, {%2,%3,%4,%5}, {%6,%7}, {%0,%1};"
                        : "+r"(acc[mt][nt][0]), "+r"(acc[mt][nt][1])
                        : "r"(a[mt][0]), "r"(a[mt][1]), "r"(a[mt][2]), "r"(a[mt][3]),
                          "r"(b0), "r"(b1));
                }
        }

#pragma unroll
        for (int mt = 0; mt < 2; ++mt)
#pragma unroll
            for (int nt = 0; nt < 4; ++nt)
#pragma unroll
                for (int h = 0; h < 2; ++h) {
                    int r_ = wm + mt * 16 + h * 8 + lrow;
                    int c0 = wn + nt * 8 + lcol;
                    float2 f = __half22float2(*(__half2*)&acc[mt][nt][h]);
                    if (!diag || r_ != c0)     s += ex2a(f.x);
                    if (!diag || r_ != c0 + 1) s += ex2a(f.y);
                }
    }

    if (!diag) s *= 2.f;

    __shared__ float red[16];
#pragma unroll
    for (int off = 16; off > 0; off >>= 1)
        s += __shfl_down_sync(0xFFFFFFFFu, s, off);
    if (lane == 0) red[wid] = s;
    __syncthreads();
    if (tid == 0) {
        float tsum = 0.f;
#pragma unroll
        for (int w = 0; w < 16; ++w) tsum += red[w];
        g_part[blockIdx.x] = tsum;
    }
}

// ---------------------------------------------------------------------------
// Kernel 3: deterministic final reduction + log
// ---------------------------------------------------------------------------
__global__ void __launch_bounds__(256) finalize_kernel(float* __restrict__ out) {
    __shared__ float red[8];
    float s = 0.f;
    for (int i = threadIdx.x; i < NTILES; i += 256) s += g_part[i];
#pragma unroll
    for (int off = 16; off > 0; off >>= 1)
        s += __shfl_down_sync(0xFFFFFFFFu, s, off);
    if ((threadIdx.x & 31) == 0) red[threadIdx.x >> 5] = s;
    __syncthreads();
    if (threadIdx.x == 0) {
        float tsum = 0.f;
#pragma unroll
        for (int w = 0; w < 8; ++w) tsum += red[w];
        out[0] = logf(tsum);
    }
}

extern "C" void kernel_launch(void* const* d_in, const int* in_sizes, int n_in,
                              void* d_out, int out_size) {
    const float* x = (const float*)d_in[0];
    float* out = (float*)d_out;
    (void)in_sizes; (void)n_in; (void)out_size;

    cudaFuncSetAttribute(simexp_kernel, cudaFuncAttributeMaxDynamicSharedMemorySize, SM_TOTAL);

    normalize_kernel<<<N_TOT / 8, 256>>>(x);
    simexp_kernel<<<NTILES, 512, SM_TOTAL>>>();
    finalize_kernel<<<1, 256>>>(out);
}

// round 15
// speedup vs baseline: 2.4903x; 2.4903x over previous
#include <cuda_runtime.h>
#include <cuda_fp16.h>
#include <math.h>
#include <stdint.h>

#define N_TOT 8192
#define F_DIM 128
#define TBLK  64                 // 8192 / 128
#define NTILES (TBLK*(TBLK+1)/2) // 2080 upper-triangle tiles
#define TILEB 32768              // 128 rows x 256B (fp16), XOR-swizzled
#define SM_TOTAL (2 * TILEB)     // A + B = 64KB

// Device scratch (allocation-free rules)
__device__ __half g_xh[N_TOT * F_DIM];   // scaled normalized feats [N][F] fp16
__device__ float g_part[NTILES];

__device__ __forceinline__ uint32_t smem_u32(const void* p) {
    uint32_t a;
    asm("{ .reg .u64 t; cvta.to.shared.u64 t, %1; cvt.u32.u64 %0, t; }" : "=r"(a) : "l"(p));
    return a;
}
__device__ __forceinline__ float ex2a(float x) {
    float y; asm("ex2.approx.f32 %0, %1;" : "=f"(y) : "f"(x)); return y;
}
#define CPA16(dst, src) \
    asm volatile("cp.async.cg.shared.global [%0], [%1], 16;" :: "r"(dst), "l"(src))

// ---------------------------------------------------------------------------
// Kernel 1: normalize + fold sqrt(10/ln2) + fp16 convert.
// Block = 32 rows. Warp w owns features w*16..w*16+15; lane owns row thw0+lane.
// 16 fully-coalesced 128B-line LDG per thread (MLP=16), register transpose.
// ---------------------------------------------------------------------------
__global__ void __launch_bounds__(256) normalize_kernel(const float* __restrict__ x) {
    __shared__ float ssp[8][33];

    const int tid  = threadIdx.x;
    const int w    = tid >> 5;      // warp: feature group
    const int lane = tid & 31;      // row within block
    const int n0   = blockIdx.x * 32;
    const int b    = n0 >> 10;
    const int thw0 = n0 & 1023;
    const float* base = x + (size_t)b * 131072 + thw0 + lane;

    float v[16];
    float ss = 0.f;
#pragma unroll
    for (int k = 0; k < 16; ++k) {
        v[k] = base[(size_t)(w * 16 + k) * 1024];   // 128B line per warp request
        ss += v[k] * v[k];
    }
    ssp[w][lane] = ss;
    __syncthreads();

    float tot = 0.f;
#pragma unroll
    for (int p = 0; p < 8; ++p) tot += ssp[p][lane];
    // 3.7982825 = sqrt(10 / ln 2): folds the exp2 scale into the data
    float rn = (1.0f / fmaxf(sqrtf(tot), 1e-12f)) * 3.7982825f;

    uint32_t* out = (uint32_t*)(g_xh + (size_t)(n0 + lane) * F_DIM) + w * 8;
#pragma unroll
    for (int k = 0; k < 8; ++k) {
        __half2 h = __floats2half2_rn(v[2 * k] * rn, v[2 * k + 1] * rn);
        out[k] = *(uint32_t*)&h;
    }
}

// ---------------------------------------------------------------------------
// Kernel 2: HMMA fp16 (f16 accumulate) 128x128x128 tile + fused exp2-sum.
// 16 warps, 32x32 warp tiles, XOR-swizzled smem (verbatim R13).
// ---------------------------------------------------------------------------
__global__ void __launch_bounds__(512, 2) simexp_kernel() {
    extern __shared__ char smem[];
    const uint32_t sbase = smem_u32(smem);
    const int tid  = threadIdx.x;
    const int wid  = tid >> 5;
    const int lane = tid & 31;

    // linear tile id -> (bi, bj), bj >= bi
    int t = blockIdx.x;
    int bi = (int)((129.0f - sqrtf(16641.0f - 8.0f * (float)t)) * 0.5f);
    while ((bi + 1) * (129 - (bi + 1)) / 2 <= t) ++bi;
    while (bi * (129 - bi) / 2 > t) --bi;
    const int bj = bi + (t - bi * (129 - bi) / 2);
    const bool diag = (bi == bj);

    // cooperative tile loads (2048 x 16B chunks over 512 threads)
    {
        const char* gA = (const char*)(g_xh + (size_t)bi * 128 * F_DIM);
#pragma unroll
        for (int it = 0; it < 4; ++it) {
            int idx = it * 512 + tid;
            int r = idx >> 4, q = idx & 15;
            CPA16(sbase + r * 256 + ((q ^ (r & 7)) << 4), gA + (size_t)idx * 16);
        }
        if (!diag) {
            const char* gB = (const char*)(g_xh + (size_t)bj * 128 * F_DIM);
#pragma unroll
            for (int it = 0; it < 4; ++it) {
                int idx = it * 512 + tid;
                int r = idx >> 4, q = idx & 15;
                CPA16(sbase + TILEB + r * 256 + ((q ^ (r & 7)) << 4), gB + (size_t)idx * 16);
            }
        }
        asm volatile("cp.async.commit_group;");
        asm volatile("cp.async.wait_group 0;" ::: "memory");
    }
    __syncthreads();

    const uint32_t aBase = sbase;
    const uint32_t bBase = diag ? sbase : (sbase + TILEB);

    const int wm = (wid >> 2) * 32;   // 4x4 warp grid
    const int wn = (wid & 3) * 32;
    const int g  = lane >> 3;
    const int lr = lane & 7;
    const int lrow = lane >> 2;
    const int lcol = (lane & 3) * 2;

    uint32_t acc[2][4][2];            // f16x2 packed accumulators
#pragma unroll
    for (int mt = 0; mt < 2; ++mt)
#pragma unroll
        for (int nt = 0; nt < 4; ++nt) {
            acc[mt][nt][0] = 0u;
            acc[mt][nt][1] = 0u;
        }

#pragma unroll
    for (int kc = 0; kc < 8; ++kc) {
        const int qa = kc * 2 + (g >> 1);
        const int qb = kc * 2 + (g & 1);
        uint32_t a[2][4];
#pragma unroll
        for (int mt = 0; mt < 2; ++mt) {
            int row = wm + mt * 16 + (g & 1) * 8 + lr;   // row & 7 == lr
            uint32_t addr = aBase + row * 256 + ((qa ^ lr) << 4);
            asm volatile("ldmatrix.sync.aligned.m8n8.x4.shared.b16 {%0,%1,%2,%3}, [%4];"
                         : "=r"(a[mt][0]), "=r"(a[mt][1]), "=r"(a[mt][2]), "=r"(a[mt][3])
                         : "r"(addr));
        }
        uint32_t bf[2][4];
#pragma unroll
        for (int np = 0; np < 2; ++np) {
            int row = wn + np * 16 + (g >> 1) * 8 + lr;  // row & 7 == lr
            uint32_t addr = bBase + row * 256 + ((qb ^ lr) << 4);
            asm volatile("ldmatrix.sync.aligned.m8n8.x4.shared.b16 {%0,%1,%2,%3}, [%4];"
                         : "=r"(bf[np][0]), "=r"(bf[np][1]), "=r"(bf[np][2]), "=r"(bf[np][3])
                         : "r"(addr));
        }
#pragma unroll
        for (int mt = 0; mt < 2; ++mt)
#pragma unroll
            for (int nt = 0; nt < 4; ++nt) {
                uint32_t b0 = bf[nt >> 1][(nt & 1) * 2];
                uint32_t b1 = bf[nt >> 1][(nt & 1) * 2 + 1];
                asm volatile(
                    "mma.sync.aligned.m16n8k16.row.col.f16.f16.f16.f16 "
                    "{%0,%1}, {%2,%3,%4,%5}, {%6,%7}, {%0,%1};"
                    : "+r"(acc[mt][nt][0]), "+r"(acc[mt][nt][1])
                    : "r"(a[mt][0]), "r"(a[mt][1]), "r"(a[mt][2]), "r"(a[mt][3]),
                      "r"(b0), "r"(b1));
            }
    }

    // epilogue: scale pre-folded -> bare 2^acc; skip i==j on diag tiles
    float s = 0.f;
#pragma unroll
    for (int mt = 0; mt < 2; ++mt)
#pragma unroll
        for (int nt = 0; nt < 4; ++nt)
#pragma unroll
            for (int h = 0; h < 2; ++h) {       // h=0: row lrow, h=1: row lrow+8
                int r_ = wm + mt * 16 + h * 8 + lrow;
                int c0 = wn + nt * 8 + lcol;
                float2 f = __half22float2(*(__half2*)&acc[mt][nt][h]);
                if (!diag || r_ != c0)     s += ex2a(f.x);
                if (!diag || r_ != c0 + 1) s += ex2a(f.y);
            }
    if (!diag) s *= 2.f;

    __shared__ float red[16];
#pragma unroll
    for (int off = 16; off > 0; off >>= 1)
        s += __shfl_down_sync(0xFFFFFFFFu, s, off);
    if (lane == 0) red[wid] = s;
    __syncthreads();
    if (tid == 0) {
        float tsum = 0.f;
#pragma unroll
        for (int w = 0; w < 16; ++w) tsum += red[w];
        g_part[blockIdx.x] = tsum;
    }
}

// ---------------------------------------------------------------------------
// Kernel 3: deterministic final reduction + log
// ---------------------------------------------------------------------------
__global__ void __launch_bounds__(256) finalize_kernel(float* __restrict__ out) {
    __shared__ float red[8];
    float s = 0.f;
    for (int i = threadIdx.x; i < NTILES; i += 256) s += g_part[i];
#pragma unroll
    for (int off = 16; off > 0; off >>= 1)
        s += __shfl_down_sync(0xFFFFFFFFu, s, off);
    if ((threadIdx.x & 31) == 0) red[threadIdx.x >> 5] = s;
    __syncthreads();
    if (threadIdx.x == 0) {
        float tsum = 0.f;
#pragma unroll
        for (int w = 0; w < 8; ++w) tsum += red[w];
        out[0] = logf(tsum);
    }
}

extern "C" void kernel_launch(void* const* d_in, const int* in_sizes, int n_in,
                              void* d_out, int out_size) {
    const float* x = (const float*)d_in[0];
    float* out = (float*)d_out;
    (void)in_sizes; (void)n_in; (void)out_size;

    cudaFuncSetAttribute(simexp_kernel, cudaFuncAttributeMaxDynamicSharedMemorySize, SM_TOTAL);

    normalize_kernel<<<N_TOT / 32, 256>>>(x);
    simexp_kernel<<<NTILES, 512, SM_TOTAL>>>();
    finalize_kernel<<<1, 256>>>(out);
}

// round 16
// speedup vs baseline: 2.5706x; 1.0322x over previous
#include <cuda_runtime.h>
#include <cuda_fp16.h>
#include <math.h>
#include <stdint.h>

#define N_TOT 8192
#define F_DIM 128
#define TBLK  64                 // 8192 / 128
#define NTILES (TBLK*(TBLK+1)/2) // 2080 upper-triangle tiles
#define TILEB 32768              // 128 rows x 256B (fp16), XOR-swizzled
#define SM_TOTAL (2 * TILEB)     // A + B = 64KB

// Device scratch (allocation-free rules)
__device__ __half g_xh[N_TOT * F_DIM];   // scaled normalized feats [N][F] fp16
__device__ float g_part[NTILES];

__device__ __forceinline__ uint32_t smem_u32(const void* p) {
    uint32_t a;
    asm("{ .reg .u64 t; cvta.to.shared.u64 t, %1; cvt.u32.u64 %0, t; }" : "=r"(a) : "l"(p));
    return a;
}
__device__ __forceinline__ float ex2a(float x) {
    float y; asm("ex2.approx.f32 %0, %1;" : "=f"(y) : "f"(x)); return y;
}
#define CPA16(dst, src) \
    asm volatile("cp.async.cg.shared.global [%0], [%1], 16;" :: "r"(dst), "l"(src))

// ---------------------------------------------------------------------------
// Kernel 1: normalize + fold sqrt(10/ln2) + fp16 convert.
// Block = 32 rows. Warp w owns features w*16..w*16+15; lane owns row thw0+lane.
// 16 fully-coalesced 128B-line LDG per thread (MLP=16), register transpose.
// ---------------------------------------------------------------------------
__global__ void __launch_bounds__(256) normalize_kernel(const float* __restrict__ x) {
    __shared__ float ssp[8][33];

    const int tid  = threadIdx.x;
    const int w    = tid >> 5;      // warp: feature group
    const int lane = tid & 31;      // row within block
    const int n0   = blockIdx.x * 32;
    const int b    = n0 >> 10;
    const int thw0 = n0 & 1023;
    const float* base = x + (size_t)b * 131072 + thw0 + lane;

    float v[16];
    float ss = 0.f;
#pragma unroll
    for (int k = 0; k < 16; ++k) {
        v[k] = base[(size_t)(w * 16 + k) * 1024];   // 128B line per warp request
        ss += v[k] * v[k];
    }
    ssp[w][lane] = ss;
    __syncthreads();

    float tot = 0.f;
#pragma unroll
    for (int p = 0; p < 8; ++p) tot += ssp[p][lane];
    // 3.7982825 = sqrt(10 / ln 2): folds the exp2 scale into the data
    float rn = (1.0f / fmaxf(sqrtf(tot), 1e-12f)) * 3.7982825f;

    uint32_t* out = (uint32_t*)(g_xh + (size_t)(n0 + lane) * F_DIM) + w * 8;
#pragma unroll
    for (int k = 0; k < 8; ++k) {
        __half2 h = __floats2half2_rn(v[2 * k] * rn, v[2 * k + 1] * rn);
        out[k] = *(uint32_t*)&h;
    }
}

// ---------------------------------------------------------------------------
// Kernel 2: HMMA fp16 (f16 accumulate) 128x128x128 tile + fused exp2-sum.
// 16 warps, 32x32 warp tiles, XOR-swizzled smem (verbatim R13).
// ---------------------------------------------------------------------------
__global__ void __launch_bounds__(512, 2) simexp_kernel() {
    extern __shared__ char smem[];
    const uint32_t sbase = smem_u32(smem);
    const int tid  = threadIdx.x;
    const int wid  = tid >> 5;
    const int lane = tid & 31;

    // linear tile id -> (bi, bj), bj >= bi
    int t = blockIdx.x;
    int bi = (int)((129.0f - sqrtf(16641.0f - 8.0f * (float)t)) * 0.5f);
    while ((bi + 1) * (129 - (bi + 1)) / 2 <= t) ++bi;
    while (bi * (129 - bi) / 2 > t) --bi;
    const int bj = bi + (t - bi * (129 - bi) / 2);
    const bool diag = (bi == bj);

    // cooperative tile loads (2048 x 16B chunks over 512 threads)
    {
        const char* gA = (const char*)(g_xh + (size_t)bi * 128 * F_DIM);
#pragma unroll
        for (int it = 0; it < 4; ++it) {
            int idx = it * 512 + tid;
            int r = idx >> 4, q = idx & 15;
            CPA16(sbase + r * 256 + ((q ^ (r & 7)) << 4), gA + (size_t)idx * 16);
        }
        if (!diag) {
            const char* gB = (const char*)(g_xh + (size_t)bj * 128 * F_DIM);
#pragma unroll
            for (int it = 0; it < 4; ++it) {
                int idx = it * 512 + tid;
                int r = idx >> 4, q = idx & 15;
                CPA16(sbase + TILEB + r * 256 + ((q ^ (r & 7)) << 4), gB + (size_t)idx * 16);
            }
        }
        asm volatile("cp.async.commit_group;");
        asm volatile("cp.async.wait_group 0;" ::: "memory");
    }
    __syncthreads();

    const uint32_t aBase = sbase;
    const uint32_t bBase = diag ? sbase : (sbase + TILEB);

    const int wm = (wid >> 2) * 32;   // 4x4 warp grid
    const int wn = (wid & 3) * 32;
    const int g  = lane >> 3;
    const int lr = lane & 7;
    const int lrow = lane >> 2;
    const int lcol = (lane & 3) * 2;

    uint32_t acc[2][4][2];            // f16x2 packed accumulators
#pragma unroll
    for (int mt = 0; mt < 2; ++mt)
#pragma unroll
        for (int nt = 0; nt < 4; ++nt) {
            acc[mt][nt][0] = 0u;
            acc[mt][nt][1] = 0u;
        }

#pragma unroll
    for (int kc = 0; kc < 8; ++kc) {
        const int qa = kc * 2 + (g >> 1);
        const int qb = kc * 2 + (g & 1);
        uint32_t a[2][4];
#pragma unroll
        for (int mt = 0; mt < 2; ++mt) {
            int row = wm + mt * 16 + (g & 1) * 8 + lr;   // row & 7 == lr
            uint32_t addr = aBase + row * 256 + ((qa ^ lr) << 4);
            asm volatile("ldmatrix.sync.aligned.m8n8.x4.shared.b16 {%0,%1,%2,%3}, [%4];"
                         : "=r"(a[mt][0]), "=r"(a[mt][1]), "=r"(a[mt][2]), "=r"(a[mt][3])
                         : "r"(addr));
        }
        uint32_t bf[2][4];
#pragma unroll
        for (int np = 0; np < 2; ++np) {
            int row = wn + np * 16 + (g >> 1) * 8 + lr;  // row & 7 == lr
            uint32_t addr = bBase + row * 256 + ((qb ^ lr) << 4);
            asm volatile("ldmatrix.sync.aligned.m8n8.x4.shared.b16 {%0,%1,%2,%3}, [%4];"
                         : "=r"(bf[np][0]), "=r"(bf[np][1]), "=r"(bf[np][2]), "=r"(bf[np][3])
                         : "r"(addr));
        }
#pragma unroll
        for (int mt = 0; mt < 2; ++mt)
#pragma unroll
            for (int nt = 0; nt < 4; ++nt) {
                uint32_t b0 = bf[nt >> 1][(nt & 1) * 2];
                uint32_t b1 = bf[nt >> 1][(nt & 1) * 2 + 1];
                asm volatile(
                    "mma.sync.aligned.m16n8k16.row.col.f16.f16.f16.f16 "
                    "{%0,%1}, {%2,%3,%4,%5}, {%6,%7}, {%0,%1};"
                    : "+r"(acc[mt][nt][0]), "+r"(acc[mt][nt][1])
                    : "r"(a[mt][0]), "r"(a[mt][1]), "r"(a[mt][2]), "r"(a[mt][3]),
                      "r"(b0), "r"(b1));
            }
    }

    // epilogue: scale pre-folded -> bare 2^acc; skip i==j on diag tiles
    float s = 0.f;
#pragma unroll
    for (int mt = 0; mt < 2; ++mt)
#pragma unroll
        for (int nt = 0; nt < 4; ++nt)
#pragma unroll
            for (int h = 0; h < 2; ++h) {       // h=0: row lrow, h=1: row lrow+8
                int r_ = wm + mt * 16 + h * 8 + lrow;
                int c0 = wn + nt * 8 + lcol;
                float2 f = __half22float2(*(__half2*)&acc[mt][nt][h]);
                if (!diag || r_ != c0)     s += ex2a(f.x);
                if (!diag || r_ != c0 + 1) s += ex2a(f.y);
            }
    if (!diag) s *= 2.f;

    __shared__ float red[16];
#pragma unroll
    for (int off = 16; off > 0; off >>= 1)
        s += __shfl_down_sync(0xFFFFFFFFu, s, off);
    if (lane == 0) red[wid] = s;
    __syncthreads();
    if (tid == 0) {
        float tsum = 0.f;
#pragma unroll
        for (int w = 0; w < 16; ++w) tsum += red[w];
        g_part[blockIdx.x] = tsum;
    }
}

// ---------------------------------------------------------------------------
// Kernel 3: deterministic final reduction + log
// ---------------------------------------------------------------------------
__global__ void __launch_bounds__(256) finalize_kernel(float* __restrict__ out) {
    __shared__ float red[8];
    float s = 0.f;
    for (int i = threadIdx.x; i < NTILES; i += 256) s += g_part[i];
#pragma unroll
    for (int off = 16; off > 0; off >>= 1)
        s += __shfl_down_sync(0xFFFFFFFFu, s, off);
    if ((threadIdx.x & 31) == 0) red[threadIdx.x >> 5] = s;
    __syncthreads();
    if (threadIdx.x == 0) {
        float tsum = 0.f;
#pragma unroll
        for (int w = 0; w < 8; ++w) tsum += red[w];
        out[0] = logf(tsum);
    }
}

extern "C" void kernel_launch(void* const* d_in, const int* in_sizes, int n_in,
                              void* d_out, int out_size) {
    const float* x = (const float*)d_in[0];
    float* out = (float*)d_out;
    (void)in_sizes; (void)n_in; (void)out_size;

    cudaFuncSetAttribute(simexp_kernel, cudaFuncAttributeMaxDynamicSharedMemorySize, SM_TOTAL);

    normalize_kernel<<<N_TOT / 32, 256>>>(x);
    simexp_kernel<<<NTILES, 512, SM_TOTAL>>>();
    finalize_kernel<<<1, 256>>>(out);
}